// round 3
// baseline (speedup 1.0000x reference)
#include <cuda_runtime.h>
#include <cuda_bf16.h>

#define N_NODES  400000
#define N_EDGES  6400000
#define N_GRAPHS 20000
#define F_IN     11
#define HID      32

// ---------------- scratch (device globals; no allocation allowed) ----------------
__device__ float g_deg [N_NODES];
__device__ float g_dinv[N_NODES];
__device__ float g_hs  [N_NODES * HID];   // dinv-prescaled node features
__device__ float g_acc [N_NODES * HID];   // scatter accumulator
__device__ float g_pool[N_GRAPHS * HID];  // pooled sums
__device__ float g_cnt [N_GRAPHS];        // nodes per graph

// ---------------- kernels ----------------

// init: deg=1 (self loop), pooled sums/counts = 0
__global__ void k_init() {
    int i = blockIdx.x * blockDim.x + threadIdx.x;
    if (i < N_GRAPHS * HID) g_pool[i] = 0.f;
    if (i < N_GRAPHS)       g_cnt[i]  = 0.f;
    if (i < N_NODES)        g_deg[i]  = 1.f;
}

// degree over dst endpoints (streaming read of the edge list)
__global__ void k_deg(const int* __restrict__ dst) {
    int e = blockIdx.x * blockDim.x + threadIdx.x;
    if (e < N_EDGES) atomicAdd(&g_deg[__ldcs(dst + e)], 1.f);
}

// layer1 GEMM: hs[n][:] = (x[n] @ W1) * dinv[n]; acc[n][:] = 0; store dinv
__global__ void k_gemm1(const float* __restrict__ x, const float* __restrict__ W1) {
    __shared__ float sW[F_IN * HID];
    __shared__ float sx[8 * F_IN];
    int t = threadIdx.x;
    for (int i = t; i < F_IN * HID; i += 256) sW[i] = W1[i];   // 352 elems > 256 threads
    int nbase = blockIdx.x * 8;
    if (t < 8 * F_IN) {
        int nn = t / F_IN, k = t % F_IN;
        int node = nbase + nn;
        sx[t] = (node < N_NODES) ? x[node * F_IN + k] : 0.f;
    }
    __syncthreads();
    int nn = t >> 5, j = t & 31;
    int node = nbase + nn;
    if (node >= N_NODES) return;
    float s = 0.f;
#pragma unroll
    for (int k = 0; k < F_IN; k++) s += sx[nn * F_IN + k] * sW[k * HID + j];
    float dinv = rsqrtf(g_deg[node]);
    if (j == 0) g_dinv[node] = dinv;
    g_hs [node * HID + j] = s * dinv;
    g_acc[node * HID + j] = 0.f;
}

// edge scatter: acc[dst][:] += hs[src][:]  (8 threads/edge, float4 vector reduction)
// Edge indices read with evict-first policy so they don't displace the
// L2-resident node arrays (g_hs/g_acc, 102 MB vs 126 MB L2).
__global__ void k_scatter(const int* __restrict__ src, const int* __restrict__ dst) {
    unsigned t = blockIdx.x * blockDim.x + threadIdx.x;
    int e = t >> 3;
    int q = t & 7;
    if (e >= N_EDGES) return;
    int s = __ldcs(src + e);
    int d = __ldcs(dst + e);
    float4 v = *reinterpret_cast<const float4*>(g_hs + (size_t)s * HID + q * 4);
    float4* p = reinterpret_cast<float4*>(g_acc + (size_t)d * HID + q * 4);
#if __CUDA_ARCH__ >= 900
    atomicAdd(p, v);                       // RED.E.ADD.F32x4 (return unused)
#else
    atomicAdd(&p->x, v.x); atomicAdd(&p->y, v.y);
    atomicAdd(&p->z, v.z); atomicAdd(&p->w, v.w);
#endif
}

// epilogue1 + layer2 GEMM (warp per node):
// h = relu(dinv*(acc+hs) + b1);  hs <- (h @ W2)*dinv;  acc <- 0
__global__ void k_mid(const float* __restrict__ b1, const float* __restrict__ W2) {
    __shared__ float sW[HID * HID];
    int t = threadIdx.x;
    for (int i = t; i < HID * HID; i += 256) sW[i] = W2[i];
    __syncthreads();
    int node = blockIdx.x * 8 + (t >> 5);
    int j = t & 31;
    if (node >= N_NODES) return;
    float dinv = g_dinv[node];
    float h = fmaxf(dinv * (g_acc[node * HID + j] + g_hs[node * HID + j]) + b1[j], 0.f);
    float s = 0.f;
#pragma unroll
    for (int k = 0; k < HID; k++)
        s += __shfl_sync(0xffffffffu, h, k) * sW[k * HID + j];
    g_hs [node * HID + j] = s * dinv;
    g_acc[node * HID + j] = 0.f;
}

// epilogue2 + mean-pool accumulation (warp per node)
__global__ void k_pool(const float* __restrict__ b2, const int* __restrict__ batch) {
    int t = threadIdx.x;
    int node = blockIdx.x * 8 + (t >> 5);
    int j = t & 31;
    if (node >= N_NODES) return;
    float dinv = g_dinv[node];
    float o = dinv * (g_acc[node * HID + j] + g_hs[node * HID + j]) + b2[j];
    int g = batch[node];
    atomicAdd(&g_pool[g * HID + j], o);
    if (j == 0) atomicAdd(&g_cnt[g], 1.f);
}

// final MLP (warp per graph): out = relu(mean @ fcW1 + fcb1) @ fcW2 + fcb2
__global__ void k_mlp(const float* __restrict__ fcW1, const float* __restrict__ fcb1,
                      const float* __restrict__ fcW2, const float* __restrict__ fcb2,
                      float* __restrict__ out) {
    __shared__ float sW[HID * HID];
    __shared__ float sw2[HID];
    int t = threadIdx.x;
    for (int i = t; i < HID * HID; i += 256) sW[i] = fcW1[i];
    if (t < HID) sw2[t] = fcW2[t];
    __syncthreads();
    int g = blockIdx.x * 8 + (t >> 5);
    int j = t & 31;
    if (g >= N_GRAPHS) return;
    float c = fmaxf(g_cnt[g], 1.f);
    float p = g_pool[g * HID + j] / c;
    float s = fcb1[j];
#pragma unroll
    for (int k = 0; k < HID; k++)
        s += __shfl_sync(0xffffffffu, p, k) * sW[k * HID + j];
    s = fmaxf(s, 0.f);
    float v = s * sw2[j];
#pragma unroll
    for (int o = 16; o > 0; o >>= 1) v += __shfl_xor_sync(0xffffffffu, v, o);
    if (j == 0) out[g] = v + fcb2[0];
}

// ---------------- launch ----------------
extern "C" void kernel_launch(void* const* d_in, const int* in_sizes, int n_in,
                              void* d_out, int out_size) {
    const float* x     = (const float*)d_in[0];
    const int*   ei    = (const int*)  d_in[1];
    const int*   batch = (const int*)  d_in[2];
    const float* W1    = (const float*)d_in[3];
    const float* b1    = (const float*)d_in[4];
    const float* W2    = (const float*)d_in[5];
    const float* b2    = (const float*)d_in[6];
    const float* fcW1  = (const float*)d_in[7];
    const float* fcb1  = (const float*)d_in[8];
    const float* fcW2  = (const float*)d_in[9];
    const float* fcb2  = (const float*)d_in[10];
    const int* src = ei;
    const int* dst = ei + N_EDGES;
    float* out = (float*)d_out;

    const int TB = 256;
    int init_n = N_GRAPHS * HID;  // 640000 >= N_NODES, N_GRAPHS
    k_init<<<(init_n + TB - 1) / TB, TB>>>();
    k_deg <<<(N_EDGES + TB - 1) / TB, TB>>>(dst);
    k_gemm1<<<(N_NODES + 7) / 8, TB>>>(x, W1);
    k_scatter<<<((long long)N_EDGES * 8 + TB - 1) / TB, TB>>>(src, dst);
    k_mid <<<(N_NODES + 7) / 8, TB>>>(b1, W2);
    k_scatter<<<((long long)N_EDGES * 8 + TB - 1) / TB, TB>>>(src, dst);
    k_pool<<<(N_NODES + 7) / 8, TB>>>(b2, batch);
    k_mlp <<<(N_GRAPHS + 7) / 8, TB>>>(fcW1, fcb1, fcW2, fcb2, out);
}

// round 5
// speedup vs baseline: 1.3179x; 1.3179x over previous
#include <cuda_runtime.h>
#include <cuda_bf16.h>

#define N_NODES  400000
#define N_EDGES  6400000
#define N_GRAPHS 20000
#define F_IN     11
#define HID      32

// ---------------- scratch (device globals; no allocation allowed) ----------------
__device__ float g_deg [N_NODES];
__device__ float g_dinv[N_NODES];
__device__ float g_hs  [N_NODES * HID];   // dinv-prescaled node features (gather source)
__device__ float g_acc [N_NODES * HID];   // scatter accumulator (init = hs: self-loop folded)
__device__ float g_pool[N_GRAPHS * HID];  // pooled sums
__device__ float g_cnt [N_GRAPHS];        // nodes per graph

// ---------------- kernels ----------------

// init: deg=1 (self loop), pooled sums/counts = 0
__global__ void k_init() {
    int i = blockIdx.x * blockDim.x + threadIdx.x;
    if (i < N_GRAPHS * HID) g_pool[i] = 0.f;
    if (i < N_GRAPHS)       g_cnt[i]  = 0.f;
    if (i < N_NODES)        g_deg[i]  = 1.f;
}

// degree over dst endpoints: int4 loads, 4 atomics/thread
__global__ void k_deg(const int* __restrict__ dst) {
    int q = blockIdx.x * blockDim.x + threadIdx.x;   // quad index
    if (q >= N_EDGES / 4) return;
    int4 d4 = __ldcs(reinterpret_cast<const int4*>(dst) + q);
    atomicAdd(&g_deg[d4.x], 1.f);
    atomicAdd(&g_deg[d4.y], 1.f);
    atomicAdd(&g_deg[d4.z], 1.f);
    atomicAdd(&g_deg[d4.w], 1.f);
}

// layer1 GEMM: hs[n][:] = (x[n] @ W1) * dinv[n]; acc[n][:] = hs[n][:]; store dinv
__global__ void k_gemm1(const float* __restrict__ x, const float* __restrict__ W1) {
    __shared__ float sW[F_IN * HID];
    __shared__ float sx[8 * F_IN];
    int t = threadIdx.x;
    for (int i = t; i < F_IN * HID; i += 256) sW[i] = W1[i];   // 352 elems > 256 threads
    int nbase = blockIdx.x * 8;
    if (t < 8 * F_IN) {
        int nn = t / F_IN, k = t % F_IN;
        int node = nbase + nn;
        sx[t] = (node < N_NODES) ? x[node * F_IN + k] : 0.f;
    }
    __syncthreads();
    int nn = t >> 5, j = t & 31;
    int node = nbase + nn;
    if (node >= N_NODES) return;
    float s = 0.f;
#pragma unroll
    for (int k = 0; k < F_IN; k++) s += sx[nn * F_IN + k] * sW[k * HID + j];
    float dinv = rsqrtf(g_deg[node]);
    if (j == 0) g_dinv[node] = dinv;
    float v = s * dinv;
    g_hs [node * HID + j] = v;
    g_acc[node * HID + j] = v;   // self-loop contribution pre-seeded
}

// edge scatter: acc[dst][:] += hs[src][:]
// 8 threads per edge (one float4 lane each), 4 edges per 8-thread group.
// 4 independent gather->RED chains per thread => MLP ~5 (incl. index int4 loads).
__global__ void k_scatter(const int* __restrict__ src, const int* __restrict__ dst) {
    unsigned t = blockIdx.x * blockDim.x + threadIdx.x;
    unsigned grp = t >> 3;          // edge-quad index
    int q = t & 7;                  // float4 lane within the 32-float row
    unsigned e0 = grp * 4;
    if (e0 >= N_EDGES) return;
    int4 s4 = __ldcs(reinterpret_cast<const int4*>(src + e0));
    int4 d4 = __ldcs(reinterpret_cast<const int4*>(dst + e0));
    const float4* hs4 = reinterpret_cast<const float4*>(g_hs);
    float4*       ac4 = reinterpret_cast<float4*>(g_acc);
    // issue all 4 gathers first (independent), then 4 vector reductions
    float4 v0 = hs4[(size_t)s4.x * 8 + q];
    float4 v1 = hs4[(size_t)s4.y * 8 + q];
    float4 v2 = hs4[(size_t)s4.z * 8 + q];
    float4 v3 = hs4[(size_t)s4.w * 8 + q];
#if __CUDA_ARCH__ >= 900
    atomicAdd(&ac4[(size_t)d4.x * 8 + q], v0);   // RED.E.ADD.F32x4
    atomicAdd(&ac4[(size_t)d4.y * 8 + q], v1);
    atomicAdd(&ac4[(size_t)d4.z * 8 + q], v2);
    atomicAdd(&ac4[(size_t)d4.w * 8 + q], v3);
#else
    float* a0 = &ac4[(size_t)d4.x * 8 + q].x;
    atomicAdd(a0+0, v0.x); atomicAdd(a0+1, v0.y); atomicAdd(a0+2, v0.z); atomicAdd(a0+3, v0.w);
    float* a1 = &ac4[(size_t)d4.y * 8 + q].x;
    atomicAdd(a1+0, v1.x); atomicAdd(a1+1, v1.y); atomicAdd(a1+2, v1.z); atomicAdd(a1+3, v1.w);
    float* a2 = &ac4[(size_t)d4.z * 8 + q].x;
    atomicAdd(a2+0, v2.x); atomicAdd(a2+1, v2.y); atomicAdd(a2+2, v2.z); atomicAdd(a2+3, v2.w);
    float* a3 = &ac4[(size_t)d4.w * 8 + q].x;
    atomicAdd(a3+0, v3.x); atomicAdd(a3+1, v3.y); atomicAdd(a3+2, v3.z); atomicAdd(a3+3, v3.w);
#endif
}

// epilogue1 + layer2 GEMM (warp per node):
// h = relu(dinv*acc + b1);  hs <- (h @ W2)*dinv;  acc <- hs (self-loop pre-seed)
__global__ void k_mid(const float* __restrict__ b1, const float* __restrict__ W2) {
    __shared__ float sW[HID * HID];
    int t = threadIdx.x;
    for (int i = t; i < HID * HID; i += 256) sW[i] = W2[i];
    __syncthreads();
    int node = blockIdx.x * 8 + (t >> 5);
    int j = t & 31;
    if (node >= N_NODES) return;
    float dinv = g_dinv[node];
    float h = fmaxf(dinv * g_acc[node * HID + j] + b1[j], 0.f);
    float s = 0.f;
#pragma unroll
    for (int k = 0; k < HID; k++)
        s += __shfl_sync(0xffffffffu, h, k) * sW[k * HID + j];
    float v = s * dinv;
    g_hs [node * HID + j] = v;
    g_acc[node * HID + j] = v;
}

// epilogue2 + mean-pool accumulation.
// One warp handles 8 consecutive nodes (j-lane = feature, loop over nn).
// batch is sorted: if all 8 nodes share one graph, reduce in registers and
// issue 32+1 atomics per 8 nodes instead of per node.
__global__ void k_pool(const float* __restrict__ b2, const int* __restrict__ batch) {
    int t = threadIdx.x;
    int warp = t >> 5;             // 8 warps/block
    int j = t & 31;
    int nbase = (blockIdx.x * 8 + warp) * 8;   // 8 nodes per warp
    if (nbase >= N_NODES) return;
    float bj = b2[j];
    int g0 = batch[nbase];
    int nend = min(nbase + 8, N_NODES);
    int glast = batch[nend - 1];
    if (g0 == glast) {
        // common case: all 8 nodes in one graph — register-reduce then one atomic set
        float sum = 0.f;
        int cnt = 0;
        for (int node = nbase; node < nend; node++) {
            float dinv = g_dinv[node];
            sum += dinv * g_acc[node * HID + j] + bj;
            cnt++;
        }
        atomicAdd(&g_pool[g0 * HID + j], sum);
        if (j == 0) atomicAdd(&g_cnt[g0], (float)cnt);
    } else {
        for (int node = nbase; node < nend; node++) {
            float dinv = g_dinv[node];
            float o = dinv * g_acc[node * HID + j] + bj;
            int g = batch[node];
            atomicAdd(&g_pool[g * HID + j], o);
            if (j == 0) atomicAdd(&g_cnt[g], 1.f);
        }
    }
}

// final MLP (warp per graph): out = relu(mean @ fcW1 + fcb1) @ fcW2 + fcb2
__global__ void k_mlp(const float* __restrict__ fcW1, const float* __restrict__ fcb1,
                      const float* __restrict__ fcW2, const float* __restrict__ fcb2,
                      float* __restrict__ out) {
    __shared__ float sW[HID * HID];
    __shared__ float sw2[HID];
    int t = threadIdx.x;
    for (int i = t; i < HID * HID; i += 256) sW[i] = fcW1[i];
    if (t < HID) sw2[t] = fcW2[t];
    __syncthreads();
    int g = blockIdx.x * 8 + (t >> 5);
    int j = t & 31;
    if (g >= N_GRAPHS) return;
    float c = fmaxf(g_cnt[g], 1.f);
    float p = g_pool[g * HID + j] / c;
    float s = fcb1[j];
#pragma unroll
    for (int k = 0; k < HID; k++)
        s += __shfl_sync(0xffffffffu, p, k) * sW[k * HID + j];
    s = fmaxf(s, 0.f);
    float v = s * sw2[j];
#pragma unroll
    for (int o = 16; o > 0; o >>= 1) v += __shfl_xor_sync(0xffffffffu, v, o);
    if (j == 0) out[g] = v + fcb2[0];
}

// ---------------- launch ----------------
extern "C" void kernel_launch(void* const* d_in, const int* in_sizes, int n_in,
                              void* d_out, int out_size) {
    const float* x     = (const float*)d_in[0];
    const int*   ei    = (const int*)  d_in[1];
    const int*   batch = (const int*)  d_in[2];
    const float* W1    = (const float*)d_in[3];
    const float* b1    = (const float*)d_in[4];
    const float* W2    = (const float*)d_in[5];
    const float* b2    = (const float*)d_in[6];
    const float* fcW1  = (const float*)d_in[7];
    const float* fcb1  = (const float*)d_in[8];
    const float* fcW2  = (const float*)d_in[9];
    const float* fcb2  = (const float*)d_in[10];
    const int* src = ei;
    const int* dst = ei + N_EDGES;
    float* out = (float*)d_out;

    const int TB = 256;
    int init_n = N_GRAPHS * HID;  // 640000 >= N_NODES, N_GRAPHS
    k_init<<<(init_n + TB - 1) / TB, TB>>>();
    k_deg <<<(N_EDGES / 4 + TB - 1) / TB, TB>>>(dst);
    k_gemm1<<<(N_NODES + 7) / 8, TB>>>(x, W1);
    long long sc_threads = (long long)(N_EDGES / 4) * 8;   // 12.8M
    k_scatter<<<(unsigned)((sc_threads + TB - 1) / TB), TB>>>(src, dst);
    k_mid <<<(N_NODES + 7) / 8, TB>>>(b1, W2);
    k_scatter<<<(unsigned)((sc_threads + TB - 1) / TB), TB>>>(src, dst);
    k_pool<<<(N_NODES + 63) / 64, TB>>>(b2, batch);
    k_mlp <<<(N_GRAPHS + 7) / 8, TB>>>(fcW1, fcb1, fcW2, fcb2, out);
}

// round 11
// speedup vs baseline: 1.3540x; 1.0274x over previous
#include <cuda_runtime.h>
#include <cuda_fp16.h>
#include <cuda_bf16.h>

#define N_NODES  400000
#define N_EDGES  6400000
#define N_GRAPHS 20000
#define F_IN     11
#define HID      32
#define NBLK_SCAN ((N_NODES + 1023) / 1024)   // 391

// ---------------- scratch (device globals; no allocation allowed) ----------------
__device__ int    g_ideg  [N_NODES];          // in-degree incl. self loop
__device__ int    g_ptr   [N_NODES];          // CSR row start (real edges only)
__device__ int    g_cursor[N_NODES];          // fill cursor
__device__ int    g_col   [N_EDGES];          // CSR column (src) indices
__device__ int    g_bsum  [NBLK_SCAN];        // scan block sums
__device__ float  g_dinv  [N_NODES];
__device__ __half g_h1    [N_NODES * HID];    // layer-1 prescaled messages (fp16)
__device__ __half g_h2    [N_NODES * HID];    // layer-2 prescaled messages (fp16)
__device__ float  g_pool  [N_GRAPHS * HID];
__device__ float  g_cnt   [N_GRAPHS];

// ---------------- kernels ----------------

__global__ void k_init() {
    int i = blockIdx.x * blockDim.x + threadIdx.x;
    if (i < N_GRAPHS * HID) g_pool[i] = 0.f;
    if (i < N_GRAPHS)       g_cnt[i]  = 0.f;
    if (i < N_NODES)        g_ideg[i] = 1;     // self loop
}

// in-degree histogram: int4 loads, 4 atomics/thread
__global__ void k_deg(const int* __restrict__ dst) {
    int q = blockIdx.x * blockDim.x + threadIdx.x;
    if (q >= N_EDGES / 4) return;
    int4 d4 = __ldcs(reinterpret_cast<const int4*>(dst) + q);
    atomicAdd(&g_ideg[d4.x], 1);
    atomicAdd(&g_ideg[d4.y], 1);
    atomicAdd(&g_ideg[d4.z], 1);
    atomicAdd(&g_ideg[d4.w], 1);
}

// scan pass 1: per-block exclusive scan of (ideg-1), block totals to g_bsum
__global__ void k_scan1() {
    __shared__ int s[1024];
    int t = threadIdx.x;
    int i = blockIdx.x * 1024 + t;
    int v = (i < N_NODES) ? g_ideg[i] - 1 : 0;
    s[t] = v;
    __syncthreads();
    for (int off = 1; off < 1024; off <<= 1) {
        int add = (t >= off) ? s[t - off] : 0;
        __syncthreads();
        s[t] += add;
        __syncthreads();
    }
    if (i < N_NODES) g_ptr[i] = s[t] - v;          // exclusive, pre-offset
    if (t == 1023)   g_bsum[blockIdx.x] = s[1023]; // block total
}

// scan pass 2: exclusive scan of block sums (single block, 512 threads)
__global__ void k_scan2() {
    __shared__ int s[512];
    int t = threadIdx.x;
    int v = (t < NBLK_SCAN) ? g_bsum[t] : 0;
    s[t] = v;
    __syncthreads();
    for (int off = 1; off < 512; off <<= 1) {
        int add = (t >= off) ? s[t - off] : 0;
        __syncthreads();
        s[t] += add;
        __syncthreads();
    }
    if (t < NBLK_SCAN) g_bsum[t] = s[t] - v;       // exclusive offsets
}

// scan pass 3: add block offsets; init cursor
__global__ void k_scan3() {
    int i = blockIdx.x * blockDim.x + threadIdx.x;
    if (i >= N_NODES) return;
    int p = g_ptr[i] + g_bsum[i >> 10];
    g_ptr[i] = p;
    g_cursor[i] = p;
}

// CSR fill: col[pos(dst)] = src
__global__ void k_csr(const int* __restrict__ src, const int* __restrict__ dst) {
    int q = blockIdx.x * blockDim.x + threadIdx.x;
    if (q >= N_EDGES / 4) return;
    int4 s4 = __ldcs(reinterpret_cast<const int4*>(src) + q);
    int4 d4 = __ldcs(reinterpret_cast<const int4*>(dst) + q);
    int p;
    p = atomicAdd(&g_cursor[d4.x], 1); g_col[p] = s4.x;
    p = atomicAdd(&g_cursor[d4.y], 1); g_col[p] = s4.y;
    p = atomicAdd(&g_cursor[d4.z], 1); g_col[p] = s4.z;
    p = atomicAdd(&g_cursor[d4.w], 1); g_col[p] = s4.w;
}

// layer1 GEMM: h1[n][:] = half((x[n] @ W1) * dinv[n]); store dinv
__global__ void k_gemm1(const float* __restrict__ x, const float* __restrict__ W1) {
    __shared__ float sW[F_IN * HID];
    __shared__ float sx[8 * F_IN];
    int t = threadIdx.x;
    for (int i = t; i < F_IN * HID; i += 256) sW[i] = W1[i];
    int nbase = blockIdx.x * 8;
    if (t < 8 * F_IN) {
        int nn = t / F_IN, k = t % F_IN;
        int node = nbase + nn;
        sx[t] = (node < N_NODES) ? x[node * F_IN + k] : 0.f;
    }
    __syncthreads();
    int nn = t >> 5, j = t & 31;
    int node = nbase + nn;
    if (node >= N_NODES) return;
    float s = 0.f;
#pragma unroll
    for (int k = 0; k < F_IN; k++) s += sx[nn * F_IN + k] * sW[k * HID + j];
    float dinv = rsqrtf((float)g_ideg[node]);
    if (j == 0) g_dinv[node] = dinv;
    g_h1[node * HID + j] = __float2half_rn(s * dinv);
}

// warp-cooperative neighbor-row sum: 4 independent gather chains +
// software-pipelined index loads (next batch's LDG in flight during current sums).
__device__ __forceinline__ float pull_sum(const __half* __restrict__ h,
                                          int start, int cnt, int j) {
    float s0 = 0.f, s1 = 0.f, s2 = 0.f, s3 = 0.f;
    int idx = (j < cnt) ? __ldg(g_col + start + j) : 0;   // prefetch batch 0
    for (int base = 0; base < cnt; base += 32) {
        int m = min(32, cnt - base);
        int cur = idx;
        int nb = base + 32;
        if (nb < cnt)                                      // prefetch next batch
            idx = (nb + j < cnt) ? __ldg(g_col + start + nb + j) : 0;
        int k = 0;
        for (; k + 4 <= m; k += 4) {
            int a = __shfl_sync(0xffffffffu, cur, k);
            int b = __shfl_sync(0xffffffffu, cur, k + 1);
            int c = __shfl_sync(0xffffffffu, cur, k + 2);
            int d = __shfl_sync(0xffffffffu, cur, k + 3);
            s0 += __half2float(__ldg(h + a * HID + j));
            s1 += __half2float(__ldg(h + b * HID + j));
            s2 += __half2float(__ldg(h + c * HID + j));
            s3 += __half2float(__ldg(h + d * HID + j));
        }
        for (; k < m; k++) {
            int a = __shfl_sync(0xffffffffu, cur, k);
            s0 += __half2float(__ldg(h + a * HID + j));
        }
    }
    return (s0 + s1) + (s2 + s3);
}

// pull aggregation 1 + epilogue + layer-2 GEMM (warp per node, lane = feature):
// agg = h1[n] + sum_{e in CSR(n)} h1[col[e]];  h = relu(dinv*agg + b1)
// h2[n][:] = half((h @ W2) * dinv)
__global__ void k_pull1(const float* __restrict__ b1, const float* __restrict__ W2) {
    __shared__ float sW[HID * HID];
    int t = threadIdx.x;
    for (int i = t; i < HID * HID; i += 256) sW[i] = W2[i];
    __syncthreads();
    int node = blockIdx.x * 8 + (t >> 5);
    int j = t & 31;
    if (node >= N_NODES) return;
    int start = g_ptr[node];
    int cnt   = g_ideg[node] - 1;
    float sum = __half2float(g_h1[node * HID + j]) + pull_sum(g_h1, start, cnt, j);
    float dinv = g_dinv[node];
    float h = fmaxf(dinv * sum + b1[j], 0.f);
    float s2 = 0.f;
#pragma unroll
    for (int k = 0; k < HID; k++)
        s2 += __shfl_sync(0xffffffffu, h, k) * sW[k * HID + j];
    g_h2[node * HID + j] = __float2half_rn(s2 * dinv);
}

// pull aggregation 2 + epilogue + mean-pool accumulation (warp per node)
__global__ void k_pull2(const float* __restrict__ b2, const int* __restrict__ batch) {
    int t = threadIdx.x;
    int node = blockIdx.x * 8 + (t >> 5);
    int j = t & 31;
    if (node >= N_NODES) return;
    int start = g_ptr[node];
    int cnt   = g_ideg[node] - 1;
    float sum = __half2float(g_h2[node * HID + j]) + pull_sum(g_h2, start, cnt, j);
    float dinv = g_dinv[node];
    float o = dinv * sum + b2[j];
    int g = batch[node];
    atomicAdd(&g_pool[g * HID + j], o);
    if (j == 0) atomicAdd(&g_cnt[g], 1.f);
}

// final MLP (warp per graph): out = relu(mean @ fcW1 + fcb1) @ fcW2 + fcb2
__global__ void k_mlp(const float* __restrict__ fcW1, const float* __restrict__ fcb1,
                      const float* __restrict__ fcW2, const float* __restrict__ fcb2,
                      float* __restrict__ out) {
    __shared__ float sW[HID * HID];
    __shared__ float sw2[HID];
    int t = threadIdx.x;
    for (int i = t; i < HID * HID; i += 256) sW[i] = fcW1[i];
    if (t < HID) sw2[t] = fcW2[t];
    __syncthreads();
    int g = blockIdx.x * 8 + (t >> 5);
    int j = t & 31;
    if (g >= N_GRAPHS) return;
    float c = fmaxf(g_cnt[g], 1.f);
    float p = g_pool[g * HID + j] / c;
    float s = fcb1[j];
#pragma unroll
    for (int k = 0; k < HID; k++)
        s += __shfl_sync(0xffffffffu, p, k) * sW[k * HID + j];
    s = fmaxf(s, 0.f);
    float v = s * sw2[j];
#pragma unroll
    for (int o = 16; o > 0; o >>= 1) v += __shfl_xor_sync(0xffffffffu, v, o);
    if (j == 0) out[g] = v + fcb2[0];
}

// ---------------- launch ----------------
extern "C" void kernel_launch(void* const* d_in, const int* in_sizes, int n_in,
                              void* d_out, int out_size) {
    const float* x     = (const float*)d_in[0];
    const int*   ei    = (const int*)  d_in[1];
    const int*   batch = (const int*)  d_in[2];
    const float* W1    = (const float*)d_in[3];
    const float* b1    = (const float*)d_in[4];
    const float* W2    = (const float*)d_in[5];
    const float* b2    = (const float*)d_in[6];
    const float* fcW1  = (const float*)d_in[7];
    const float* fcb1  = (const float*)d_in[8];
    const float* fcW2  = (const float*)d_in[9];
    const float* fcb2  = (const float*)d_in[10];
    const int* src = ei;
    const int* dst = ei + N_EDGES;
    float* out = (float*)d_out;

    const int TB = 256;
    int init_n = N_GRAPHS * HID;   // 640000 >= N_NODES, N_GRAPHS
    k_init <<<(init_n + TB - 1) / TB, TB>>>();
    k_deg  <<<(N_EDGES / 4 + TB - 1) / TB, TB>>>(dst);
    k_scan1<<<NBLK_SCAN, 1024>>>();
    k_scan2<<<1, 512>>>();
    k_scan3<<<(N_NODES + TB - 1) / TB, TB>>>();
    k_csr  <<<(N_EDGES / 4 + TB - 1) / TB, TB>>>(src, dst);
    k_gemm1<<<(N_NODES + 7) / 8, TB>>>(x, W1);
    k_pull1<<<(N_NODES + 7) / 8, TB>>>(b1, W2);
    k_pull2<<<(N_NODES + 7) / 8, TB>>>(b2, batch);
    k_mlp  <<<(N_GRAPHS + 7) / 8, TB>>>(fcW1, fcb1, fcW2, fcb2, out);
}